// round 9
// baseline (speedup 1.0000x reference)
#include <cuda_runtime.h>
#include <math.h>

// Problem constants
#define N        10000
#define DF       32
#define ITERS    4
#define NPAD     10240          // padded slots (multiple of 128)
#define NCHUNK   640            // 16 j per chunk
#define JSPLIT   32             // j-range splits
#define CPS      20             // chunks per split
#define SPAIRS   160            // packed pairs per split (320 j)
#define ITILE    128
#define NITILE   80             // NPAD/128; grid 80*32 = 2560 blocks
#define NBINS    32768          // 32^3 Morton bins, cell size 1.0
#define ZSCALE   16384.0f
#define SENTC    50.0f
#define F_INF    __int_as_float(0x7F800000)

// Scratch (static device arrays; cudaMalloc is forbidden)
__device__ float  g_pairsA[(NPAD / 2) * 16];
__device__ float  g_pairsB[(NPAD / 2) * 16];
// chunk record: 3 float4 per chunk:
//  q0 = (cx, cy, cz, r3o2)        r3o2=(3.2+rc)^2
//  q1 = (r3i2, r2o2, r2i2, r1o2)  rXi2=(bw-rc)^2 if rc<bw else -1
//  q2 = (sx, sy, szi_as_float, r1i2)
__device__ float4 g_cmetaA[NCHUNK * 3];
__device__ float4 g_cmetaB[NCHUNK * 3];
__device__ int    g_perm[NPAD];
__device__ int    g_hist[NBINS];
__device__ int    g_binoff[NBINS];
__device__ int    g_cnt[ITERS * NITILE];
__device__ float  g_part[JSPLIT * NPAD * 12];
__device__ float  g_h[ITERS * N * DF];
__device__ float  g_w[ITERS * N * 3];

// ---------------------------------------------------------------------------
// Pair record (16 words per packed j-pair):
//   [0..7]  x0 x1 y0 y1 z0 z1 nu0 nu1   (nu = -0.5|x|^2)
//   [8..11] x0 y0 x1 y1                  (packed xy addends)
//   [12,13] round(z*2^14) s32
// ---------------------------------------------------------------------------
__device__ __forceinline__ void write_rec(float* buf, int s, float x, float y, float z) {
    int p = s >> 1, h = s & 1;
    float nu = -0.5f * (x * x + y * y + z * z);
    float* rec = buf + p * 16;
    rec[0 + h] = x;
    rec[2 + h] = y;
    rec[4 + h] = z;
    rec[6 + h] = nu;
    rec[8 + 2 * h] = x;
    rec[9 + 2 * h] = y;
    ((int*)rec)[12 + h] = __float2int_rn(z * ZSCALE);
}

__device__ __forceinline__ void make_chunk_rec(
    float4* dst3,
    float mnx, float mxx, float mny, float mxy, float mnz, float mxz,
    float sx, float sy, int szi
) {
    float dx = mxx - mnx, dy = mxy - mny, dz = mxz - mnz;
    float rc = 0.5f * sqrtf(dx*dx + dy*dy + dz*dz) + 1e-3f;
    float r3o = 3.2f + rc, r2o = 1.7f + rc, r1o = 0.2f + rc;
    float r3i = 3.2f - rc, r2i = 1.7f - rc, r1i = 0.2f - rc;
    float r3i2 = (r3i > 0.f) ? r3i * r3i : -1.0f;
    float r2i2 = (r2i > 0.f) ? r2i * r2i : -1.0f;
    float r1i2 = (r1i > 0.f) ? r1i * r1i : -1.0f;
    dst3[0] = make_float4(0.5f*(mnx+mxx), 0.5f*(mny+mxy), 0.5f*(mnz+mxz), r3o*r3o);
    dst3[1] = make_float4(r3i2, r2o*r2o, r2i2, r1o*r1o);
    dst3[2] = make_float4(sx, sy, __int_as_float(szi), r1i2);
}

// 3D Morton spread (5 bits used)
__device__ __forceinline__ unsigned spread3(unsigned x) {
    x &= 0x3FF;
    x = (x | (x << 16)) & 0x030000FF;
    x = (x | (x << 8))  & 0x0300F00F;
    x = (x | (x << 4))  & 0x030C30C3;
    x = (x | (x << 2))  & 0x09249249;
    return x;
}
__device__ __forceinline__ int cellkey(float x, float y, float z) {
    int cx = min(max((int)floorf(x + 16.f), 0), 31);
    int cy = min(max((int)floorf(y + 16.f), 0), 31);
    int cz = min(max((int)floorf(z + 16.f), 0), 31);
    return (int)(spread3(cx) | (spread3(cy) << 1) | (spread3(cz) << 2));
}

// ---------------------------------------------------------------------------
// Single-block sort: histogram -> scan -> scatter -> pair records -> chunk meta
// ---------------------------------------------------------------------------
__global__ void __launch_bounds__(1024, 1) sortall_kernel(const float* __restrict__ X) {
    __shared__ int aux[1024];
    int tid = threadIdx.x;

    for (int k = tid; k < NBINS; k += 1024) g_hist[k] = 0;
    if (tid < ITERS * NITILE) g_cnt[tid] = 0;
    __syncthreads();

    for (int i = tid; i < N; i += 1024)
        atomicAdd(&g_hist[cellkey(X[3*i], X[3*i+1], X[3*i+2])], 1);
    __syncthreads();

    int t0 = tid * 32;
    int sum = 0;
    for (int k = 0; k < 32; k++) sum += g_hist[t0 + k];
    aux[tid] = sum;
    __syncthreads();
    for (int off = 1; off < 1024; off <<= 1) {
        int v = (tid >= off) ? aux[tid - off] : 0;
        __syncthreads();
        aux[tid] += v;
        __syncthreads();
    }
    int base = aux[tid] - sum;
    for (int k = 0; k < 32; k++) {
        int h = g_hist[t0 + k];
        g_binoff[t0 + k] = base;
        base += h;
    }
    __syncthreads();

    for (int i = tid; i < N; i += 1024) {
        float x = X[3*i], y = X[3*i+1], z = X[3*i+2];
        int slot = atomicAdd(&g_binoff[cellkey(x, y, z)], 1);
        g_perm[slot] = i;
        write_rec(g_pairsA, slot, x, y, z);
    }
    for (int s = N + tid; s < NPAD; s += 1024)
        write_rec(g_pairsA, s, SENTC, SENTC, SENTC);
    __syncthreads();

    // chunk records (16 slots per chunk): bbox + sums
    for (int c = tid; c < NCHUNK; c += 1024) {
        float mnx = 1e30f, mxx = -1e30f, mny = 1e30f, mxy = -1e30f, mnz = 1e30f, mxz = -1e30f;
        float sx = 0.f, sy = 0.f;
        int szi = 0;
        for (int s = c * 16; s < c * 16 + 16; s++) {
            int p = s >> 1, h = s & 1;
            float x = g_pairsA[p*16 + 0 + h];
            float y = g_pairsA[p*16 + 2 + h];
            float z = g_pairsA[p*16 + 4 + h];
            mnx = fminf(mnx, x); mxx = fmaxf(mxx, x);
            mny = fminf(mny, y); mxy = fmaxf(mxy, y);
            mnz = fminf(mnz, z); mxz = fmaxf(mxz, z);
            sx += x; sy += y;
            szi += ((int*)g_pairsA)[p*16 + 12 + h];
        }
        make_chunk_rec(&g_cmetaA[c * 3], mnx, mxx, mny, mxy, mnz, mxz, sx, sy, szi);
    }
}

// ---------------------------------------------------------------------------
// Logits pipeline
// ---------------------------------------------------------------------------
__global__ void linear1_kernel(const float* __restrict__ Xfea,
                               const float* __restrict__ W1,
                               const float* __restrict__ b1) {
    int it = blockIdx.y;
    int n  = blockIdx.x * blockDim.x + threadIdx.x;
    __shared__ float sW[DF * DF];
    __shared__ float sb[DF];
    for (int k = threadIdx.x; k < DF * DF; k += blockDim.x) sW[k] = W1[it * DF * DF + k];
    if (threadIdx.x < DF) sb[threadIdx.x] = b1[it * DF + threadIdx.x];
    __syncthreads();
    if (n >= N) return;
    float xf[DF];
    const float4* xr = (const float4*)(Xfea + n * DF);
    #pragma unroll
    for (int q = 0; q < DF / 4; q++) {
        float4 v = xr[q];
        xf[4*q] = v.x; xf[4*q+1] = v.y; xf[4*q+2] = v.z; xf[4*q+3] = v.w;
    }
    float* hout = g_h + (it * N + n) * DF;
    #pragma unroll 4
    for (int f = 0; f < DF; f++) {
        float acc = sb[f];
        #pragma unroll
        for (int k = 0; k < DF; k++) acc = fmaf(xf[k], sW[f * DF + k], acc);
        hout[f] = acc;
    }
}

// BN stats + BN + ReLU + linear2 + exp in one pass (block = one iteration)
__global__ void __launch_bounds__(1024, 1) bnlogits_kernel(const float* __restrict__ gamma,
                                const float* __restrict__ beta,
                                const float* __restrict__ W2,
                                const float* __restrict__ b2) {
    int it = blockIdx.x;
    int tid = threadIdx.x;
    int w  = tid >> 5;
    int f  = tid & 31;
    __shared__ float ss[32 * 33];
    __shared__ float sqq[32 * 33];
    __shared__ float smu[DF], sis[DF], sg[DF], sbe[DF], sW2[3 * DF], sb2[3];

    float s = 0.f, sq = 0.f;
    for (int n = w; n < N; n += 32) {
        float v = g_h[(it * N + n) * DF + f];
        s += v;
        sq = fmaf(v, v, sq);
    }
    ss [w * 33 + f] = s;
    sqq[w * 33 + f] = sq;
    if (tid < DF) { sg[tid] = gamma[it * DF + tid]; sbe[tid] = beta[it * DF + tid]; }
    if (tid < 3 * DF) sW2[tid] = W2[it * 3 * DF + tid];
    if (tid < 3)      sb2[tid] = b2[it * 3 + tid];
    __syncthreads();
    if (tid < DF) {
        float ts = 0.f, tq = 0.f;
        for (int ww = 0; ww < 32; ww++) { ts += ss[ww * 33 + f]; tq += sqq[ww * 33 + f]; }
        float mu  = ts / (float)N;
        float var = tq / (float)N - mu * mu;   // biased var (matches reference)
        smu[tid] = mu;
        sis[tid] = rsqrtf(var + 1e-5f);
    }
    __syncthreads();

    for (int n = tid; n < N; n += 1024) {
        const float* hrow = g_h + (it * N + n) * DF;
        float l0 = sb2[0], l1 = sb2[1], l2 = sb2[2];
        #pragma unroll
        for (int k = 0; k < DF; k++) {
            float a = fmaxf((hrow[k] - smu[k]) * sis[k] * sg[k] + sbe[k], 0.f);
            l0 = fmaf(a, sW2[0 * DF + k], l0);
            l1 = fmaf(a, sW2[1 * DF + k], l1);
            l2 = fmaf(a, sW2[2 * DF + k], l2);
        }
        float m = fmaxf(l0, fmaxf(l1, l2));
        float* wout = g_w + (it * N + n) * 3;
        wout[0] = expf(l0 - m);
        wout[1] = expf(l1 - m);
        wout[2] = expf(l2 - m);
    }
}

// ---------------------------------------------------------------------------
// Mean-shift with far-field chunk aggregates + fused finalize.
// ---------------------------------------------------------------------------
__global__ void __launch_bounds__(ITILE, 7) shift_kernel(float* __restrict__ out, int it) {
    __shared__ __align__(16) float  sj[SPAIRS * 16];   // 10.2 KB pair tile
    __shared__ float4 schunk[CPS * 3];                 // 960 B chunk records
    __shared__ int s_last;

    const float*  srcP = (it & 1) ? g_pairsB : g_pairsA;
    const float4* srcM = (it & 1) ? g_cmetaB : g_cmetaA;

    int js  = blockIdx.y;
    int bx  = blockIdx.x;
    int tid = threadIdx.x;

    const float4* tsrc = (const float4*)(srcP + js * SPAIRS * 16);
    float4* d4 = (float4*)sj;
    #pragma unroll
    for (int t = tid; t < SPAIRS * 4; t += ITILE) d4[t] = tsrc[t];
    if (tid < CPS * 3) schunk[tid] = srcM[js * CPS * 3 + tid];
    __syncthreads();

    int slot = bx * ITILE + tid;
    int pb = (slot >> 1) * 16, h = slot & 1;
    float xi  = srcP[pb + 0 + h];
    float yi  = srcP[pb + 2 + h];
    float zi  = srcP[pb + 4 + h];
    float nui = srcP[pb + 6 + h];
    float th1 = -nui - 0.02f;    // bw=0.2
    float th2 = -nui - 1.445f;   // bw=1.7
    float th3 = -nui - 5.12f;    // bw=3.2

    unsigned long long xi2, yi2, zi2;
    asm("mov.b64 %0, {%1, %1};" : "=l"(xi2) : "f"(xi));
    asm("mov.b64 %0, {%1, %1};" : "=l"(yi2) : "f"(yi));
    asm("mov.b64 %0, {%1, %1};" : "=l"(zi2) : "f"(zi));

    unsigned long long axy1 = 0ull, axy2 = 0ull, axy3 = 0ull;
    int   az1 = 0, az2 = 0, az3 = 0;
    int   ac1 = 0, ac2 = 0;
    float fc3 = 0.0f;

    for (int c = 0; c < CPS; c++) {
        float4 q0 = schunk[c * 3 + 0];
        float4 q1 = schunk[c * 3 + 1];
        float4 q2 = schunk[c * 3 + 2];
        float dx = xi - q0.x, dy = yi - q0.y, dz = zi - q0.z;
        float d2 = fmaf(dx, dx, fmaf(dy, dy, dz * dz));

        // aggregate adds for fully-in bands (exact z/count; xy fp reorder ok)
        unsigned long long sxy;
        asm("mov.b64 %0, {%1, %2};" : "=l"(sxy) : "f"(q2.x), "f"(q2.y));
        int szi = __float_as_int(q2.z);
        asm("{\n\t"
            ".reg .pred p3, p2, p1;\n\t"
            "setp.le.f32 p3, %9, %10;\n\t"
            "setp.le.f32 p2, %9, %11;\n\t"
            "setp.le.f32 p1, %9, %12;\n\t"
            "@p3 add.rn.f32x2 %2, %2, %13;\n\t"
            "@p3 add.s32 %5, %5, %14;\n\t"
            "@p3 add.f32 %8, %8, 0F41800000;\n\t"
            "@p2 add.rn.f32x2 %1, %1, %13;\n\t"
            "@p2 add.s32 %4, %4, %14;\n\t"
            "@p2 add.s32 %7, %7, 16;\n\t"
            "@p1 add.rn.f32x2 %0, %0, %13;\n\t"
            "@p1 add.s32 %3, %3, %14;\n\t"
            "@p1 add.s32 %6, %6, 16;\n\t"
            "}"
            : "+l"(axy1), "+l"(axy2), "+l"(axy3),
              "+r"(az1), "+r"(az2), "+r"(az3),
              "+r"(ac1), "+r"(ac2), "+f"(fc3)
            : "f"(d2), "f"(q1.x), "f"(q1.z), "f"(q2.w),
              "l"(sxy), "r"(szi));

        bool f3 = d2 <= q1.x, f2 = d2 <= q1.z, f1 = d2 <= q2.w;
        bool needs = (d2 <= q0.w && !f3) || (d2 <= q1.y && !f2) || (d2 <= q1.w && !f1);
        if (__ballot_sync(0xFFFFFFFFu, needs)) {
            float e3 = f3 ? F_INF : th3;
            float e2 = f2 ? F_INF : th2;
            float e1 = f1 ? F_INF : th1;
            #pragma unroll
            for (int p = c * 8; p < c * 8 + 8; p++) {
                const float* rec = sj + p * 16;
                unsigned long long x01  = *(const unsigned long long*)(rec + 0);
                unsigned long long y01  = *(const unsigned long long*)(rec + 2);
                unsigned long long z01  = *(const unsigned long long*)(rec + 4);
                unsigned long long nu01 = *(const unsigned long long*)(rec + 6);
                unsigned long long xy0  = *(const unsigned long long*)(rec + 8);
                unsigned long long xy1  = *(const unsigned long long*)(rec + 10);
                int zf0 = ((const int*)rec)[12];
                int zf1 = ((const int*)rec)[13];
                asm("{\n\t"
                    ".reg .b64  t64;\n\t"
                    ".reg .f32  vl, vh;\n\t"
                    ".reg .pred pl1, pl2, pl3, ph1, ph2, ph3;\n\t"
                    "fma.rn.f32x2 t64, %9, %12, %15;\n\t"
                    "fma.rn.f32x2 t64, %10, %13, t64;\n\t"
                    "fma.rn.f32x2 t64, %11, %14, t64;\n\t"
                    "mov.b64 {vl, vh}, t64;\n\t"
                    "setp.ge.f32 pl1, vl, %16;\n\t"
                    "setp.ge.f32 pl2, vl, %17;\n\t"
                    "setp.ge.f32 pl3, vl, %18;\n\t"
                    "setp.ge.f32 ph1, vh, %16;\n\t"
                    "setp.ge.f32 ph2, vh, %17;\n\t"
                    "setp.ge.f32 ph3, vh, %18;\n\t"
                    "@pl1 add.rn.f32x2 %0, %0, %19;\n\t"
                    "@pl1 add.s32 %3, %3, %21;\n\t"
                    "@pl1 add.s32 %6, %6, 1;\n\t"
                    "@pl2 add.rn.f32x2 %1, %1, %19;\n\t"
                    "@pl2 add.s32 %4, %4, %21;\n\t"
                    "@pl2 add.s32 %7, %7, 1;\n\t"
                    "@pl3 add.rn.f32x2 %2, %2, %19;\n\t"
                    "@pl3 add.s32 %5, %5, %21;\n\t"
                    "@pl3 add.f32 %8, %8, 0F3F800000;\n\t"
                    "@ph1 add.rn.f32x2 %0, %0, %20;\n\t"
                    "@ph1 add.s32 %3, %3, %22;\n\t"
                    "@ph1 add.s32 %6, %6, 1;\n\t"
                    "@ph2 add.rn.f32x2 %1, %1, %20;\n\t"
                    "@ph2 add.s32 %4, %4, %22;\n\t"
                    "@ph2 add.s32 %7, %7, 1;\n\t"
                    "@ph3 add.rn.f32x2 %2, %2, %20;\n\t"
                    "@ph3 add.s32 %5, %5, %22;\n\t"
                    "@ph3 add.f32 %8, %8, 0F3F800000;\n\t"
                    "}"
                    : "+l"(axy1), "+l"(axy2), "+l"(axy3),
                      "+r"(az1), "+r"(az2), "+r"(az3),
                      "+r"(ac1), "+r"(ac2), "+f"(fc3)
                    : "l"(xi2), "l"(yi2), "l"(zi2),
                      "l"(x01), "l"(y01), "l"(z01), "l"(nu01),
                      "f"(e1), "f"(e2), "f"(e3),
                      "l"(xy0), "l"(xy1), "r"(zf0), "r"(zf1));
            }
        }
    }

    float* dst = g_part + (js * NPAD + slot) * 12;
    ((float4*)dst)[0] = make_float4(
        __uint_as_float((unsigned)axy1), __uint_as_float((unsigned)(axy1 >> 32)),
        __uint_as_float((unsigned)axy2), __uint_as_float((unsigned)(axy2 >> 32)));
    ((float4*)dst)[1] = make_float4(
        __uint_as_float((unsigned)axy3), __uint_as_float((unsigned)(axy3 >> 32)),
        __int_as_float(az1), __int_as_float(az2));
    ((float4*)dst)[2] = make_float4(
        __int_as_float(az3), __int_as_float(ac1),
        __int_as_float(ac2), fc3);

    // last-block finalize (R8-proven protocol: fence all, sync, then counter)
    __threadfence();
    __syncthreads();
    if (tid == 0) {
        int old = atomicAdd(&g_cnt[it * NITILE + bx], 1);
        s_last = (old == JSPLIT - 1) ? 1 : 0;
    }
    __syncthreads();
    if (!s_last) return;
    __threadfence();

    float nx = SENTC, ny = SENTC, nz = SENTC;
    if (slot < N) {
        float sx1=0,sy1=0,sx2=0,sy2=0,sx3=0,sy3=0, c3=0.f;
        int   z1=0,z2=0,z3=0, c1=0,c2=0;
        #pragma unroll 4
        for (int js2 = 0; js2 < JSPLIT; js2++) {
            const float4* p = (const float4*)(g_part + (js2 * NPAD + slot) * 12);
            float4 v0 = p[0], v1 = p[1], v2 = p[2];
            sx1 += v0.x; sy1 += v0.y; sx2 += v0.z; sy2 += v0.w;
            sx3 += v1.x; sy3 += v1.y;
            z1 += __float_as_int(v1.z); z2 += __float_as_int(v1.w);
            z3 += __float_as_int(v2.x);
            c1 += __float_as_int(v2.y); c2 += __float_as_int(v2.z); c3 += v2.w;
        }
        float sz1 = (float)z1 * (1.0f / ZSCALE);
        float sz2 = (float)z2 * (1.0f / ZSCALE);
        float sz3 = (float)z3 * (1.0f / ZSCALE);
        int o = g_perm[slot];
        const float* wp = g_w + (it * N + o) * 3;
        float e0 = wp[0], e1w = wp[1], e2w = wp[2];
        float inv = 1.0f / (e0 + e1w + e2w);
        float r1 = e0 / (float)c1, r2 = e1w / (float)c2, r3 = e2w / c3;
        nx = (sx1 * r1 + sx2 * r2 + sx3 * r3) * inv;
        ny = (sy1 * r1 + sy2 * r2 + sy3 * r3) * inv;
        nz = (sz1 * r1 + sz2 * r2 + sz3 * r3) * inv;
        float* oo = out + (it * N + o) * 3;
        oo[0] = nx; oo[1] = ny; oo[2] = nz;
    }

    if (it < ITERS - 1) {
        float*  dstP = (it & 1) ? g_pairsA : g_pairsB;
        float4* dstM = (it & 1) ? g_cmetaA : g_cmetaB;
        write_rec(dstP, slot, nx, ny, nz);
        // chunk record over 16-lane groups (chunk = 16 consecutive slots)
        float mnx = nx, mxx = nx, mny = ny, mxy = ny, mnz = nz, mxz = nz;
        float sx = nx, sy = ny;
        int   szi = __float2int_rn(nz * ZSCALE);
        #pragma unroll
        for (int off = 8; off >= 1; off >>= 1) {
            mnx = fminf(mnx, __shfl_xor_sync(0xFFFFFFFF, mnx, off));
            mxx = fmaxf(mxx, __shfl_xor_sync(0xFFFFFFFF, mxx, off));
            mny = fminf(mny, __shfl_xor_sync(0xFFFFFFFF, mny, off));
            mxy = fmaxf(mxy, __shfl_xor_sync(0xFFFFFFFF, mxy, off));
            mnz = fminf(mnz, __shfl_xor_sync(0xFFFFFFFF, mnz, off));
            mxz = fmaxf(mxz, __shfl_xor_sync(0xFFFFFFFF, mxz, off));
            sx  += __shfl_xor_sync(0xFFFFFFFF, sx, off);
            sy  += __shfl_xor_sync(0xFFFFFFFF, sy, off);
            szi += __shfl_xor_sync(0xFFFFFFFF, szi, off);
        }
        if ((tid & 15) == 0)
            make_chunk_rec(&dstM[(slot >> 4) * 3], mnx, mxx, mny, mxy, mnz, mxz, sx, sy, szi);
    }
}

// ---------------------------------------------------------------------------
// Inputs: 0:X 1:X_fea 2:W1 3:b1 4:gamma 5:beta 6:W2 7:b2   Output: [4,N,3] f32
// Launch order: shift(it=0) at index 3 (ncu capture point). 7 launches total.
// ---------------------------------------------------------------------------
extern "C" void kernel_launch(void* const* d_in, const int* in_sizes, int n_in,
                              void* d_out, int out_size) {
    const float* X     = (const float*)d_in[0];
    const float* Xfea  = (const float*)d_in[1];
    const float* W1    = (const float*)d_in[2];
    const float* b1    = (const float*)d_in[3];
    const float* gamma = (const float*)d_in[4];
    const float* beta  = (const float*)d_in[5];
    const float* W2    = (const float*)d_in[6];
    const float* b2    = (const float*)d_in[7];
    float* out = (float*)d_out;

    linear1_kernel<<<dim3((N + 127) / 128, ITERS), 128>>>(Xfea, W1, b1);   // 0
    bnlogits_kernel<<<ITERS, 1024>>>(gamma, beta, W2, b2);                 // 1
    sortall_kernel<<<1, 1024>>>(X);                                        // 2
    for (int it = 0; it < ITERS; it++)                                     // 3..6
        shift_kernel<<<dim3(NITILE, JSPLIT), ITILE>>>(out, it);
}

// round 10
// speedup vs baseline: 1.3299x; 1.3299x over previous
#include <cuda_runtime.h>
#include <math.h>

// Problem constants
#define N        10000
#define DF       32
#define ITERS    4
#define JSPLIT   16             // j-range splits
#define PCHUNK   320            // packed j-pairs per split (640 j)
#define NPAIR_PAD (JSPLIT * PCHUNK)    // 5120 pairs = 10240 slots
#define NSLOTS   (2 * NPAIR_PAD)       // 10240
#define ITILE    256
#define NITILE   40             // grid 40*16 = 640 blocks -> 1 wave @ occ 5
#define SENTC    1.0e6f

// Scratch (static device arrays; cudaMalloc is forbidden)
__device__ float g_pairsA[NPAIR_PAD * 16];   // double-buffered pair records
__device__ float g_pairsB[NPAIR_PAD * 16];
__device__ int   g_cnt[ITERS * NITILE];      // stripe completion counters
__device__ float g_part[JSPLIT * NSLOTS * 12];
__device__ float g_h[ITERS * N * DF];
__device__ float g_stats[ITERS * DF * 2];
__device__ float g_w[ITERS * N * 3];         // unnormalized softmax weights

// ---------------------------------------------------------------------------
// Pair record (16 floats per packed j-pair):
//   [0..7]   x0 x1 y0 y1 z0 z1 nu0 nu1   (nu = -0.5|x|^2, dist path)
//   [8..11]  x0 y0 x1 y1                  (xy addends, packed f32x2)
//   [12..15] z0 1.0 z1 1.0                (zc addends, packed f32x2)
// ---------------------------------------------------------------------------
__device__ __forceinline__ void write_rec(float* buf, int s, float x, float y, float z) {
    int p = s >> 1, h = s & 1;
    float nu = -0.5f * (x * x + y * y + z * z);
    float* rec = buf + p * 16;
    rec[0 + h]  = x;
    rec[2 + h]  = y;
    rec[4 + h]  = z;
    rec[6 + h]  = nu;
    rec[8  + 2 * h] = x;
    rec[9  + 2 * h] = y;
    rec[12 + 2 * h] = z;
    rec[13 + 2 * h] = 1.0f;
}

// ---------------------------------------------------------------------------
// Logits pipeline
// ---------------------------------------------------------------------------
__global__ void linear1_kernel(const float* __restrict__ Xfea,
                               const float* __restrict__ W1,
                               const float* __restrict__ b1) {
    int it = blockIdx.y;
    int n  = blockIdx.x * blockDim.x + threadIdx.x;
    __shared__ float sW[DF * DF];
    __shared__ float sb[DF];
    for (int k = threadIdx.x; k < DF * DF; k += blockDim.x) sW[k] = W1[it * DF * DF + k];
    if (threadIdx.x < DF) sb[threadIdx.x] = b1[it * DF + threadIdx.x];
    __syncthreads();
    if (n >= N) return;
    float xf[DF];
    const float4* xr = (const float4*)(Xfea + n * DF);
    #pragma unroll
    for (int q = 0; q < DF / 4; q++) {
        float4 v = xr[q];
        xf[4*q] = v.x; xf[4*q+1] = v.y; xf[4*q+2] = v.z; xf[4*q+3] = v.w;
    }
    float* hout = g_h + (it * N + n) * DF;
    #pragma unroll 4
    for (int f = 0; f < DF; f++) {
        float acc = sb[f];
        #pragma unroll
        for (int k = 0; k < DF; k++) acc = fmaf(xf[k], sW[f * DF + k], acc);
        hout[f] = acc;
    }
}

// BN stats (R4-proven) + fused prep of pair buffer A + counter reset.
__global__ void __launch_bounds__(1024, 1) bnstats_prep_kernel(const float* __restrict__ X) {
    int it = blockIdx.x;
    int tid = threadIdx.x;
    int w  = tid >> 5;
    int f  = tid & 31;
    float s = 0.f, sq = 0.f;
    for (int n = w; n < N; n += 32) {
        float v = g_h[(it * N + n) * DF + f];
        s += v;
        sq = fmaf(v, v, sq);
    }
    __shared__ float ss[32 * 33];
    __shared__ float sqq[32 * 33];
    ss [w * 33 + f] = s;
    sqq[w * 33 + f] = sq;
    __syncthreads();
    if (tid < DF) {
        float ts = 0.f, tq = 0.f;
        for (int ww = 0; ww < 32; ww++) { ts += ss[ww * 33 + f]; tq += sqq[ww * 33 + f]; }
        float mu  = ts / (float)N;
        float var = tq / (float)N - mu * mu;   // biased var (matches reference)
        g_stats[(it * DF + f) * 2 + 0] = mu;
        g_stats[(it * DF + f) * 2 + 1] = rsqrtf(var + 1e-5f);
    }
    // fused prep: build pair buffer A + sentinels + zero stripe counters
    int gtid = blockIdx.x * 1024 + tid;     // 0..4095
    for (int sl = gtid; sl < NSLOTS; sl += 4096) {
        if (sl < N) write_rec(g_pairsA, sl, X[3*sl], X[3*sl+1], X[3*sl+2]);
        else        write_rec(g_pairsA, sl, SENTC, SENTC, SENTC);
    }
    if (gtid < ITERS * NITILE) g_cnt[gtid] = 0;
}

__global__ void logits_kernel(const float* __restrict__ gamma,
                              const float* __restrict__ beta,
                              const float* __restrict__ W2,
                              const float* __restrict__ b2) {
    int it = blockIdx.y;
    int n  = blockIdx.x * blockDim.x + threadIdx.x;
    __shared__ float sg[DF], sbe[DF], smu[DF], sis[DF], sW2[3 * DF], sb2[3];
    if (threadIdx.x < DF) {
        sg [threadIdx.x] = gamma[it * DF + threadIdx.x];
        sbe[threadIdx.x] = beta [it * DF + threadIdx.x];
        smu[threadIdx.x] = g_stats[(it * DF + threadIdx.x) * 2 + 0];
        sis[threadIdx.x] = g_stats[(it * DF + threadIdx.x) * 2 + 1];
    }
    if (threadIdx.x < 3 * DF) sW2[threadIdx.x] = W2[it * 3 * DF + threadIdx.x];
    if (threadIdx.x < 3)      sb2[threadIdx.x] = b2[it * 3 + threadIdx.x];
    __syncthreads();
    if (n >= N) return;
    const float* hrow = g_h + (it * N + n) * DF;
    float a[DF];
    #pragma unroll
    for (int f = 0; f < DF; f++) {
        float v = (hrow[f] - smu[f]) * sis[f] * sg[f] + sbe[f];
        a[f] = fmaxf(v, 0.f);
    }
    float l0 = sb2[0], l1 = sb2[1], l2 = sb2[2];
    #pragma unroll
    for (int f = 0; f < DF; f++) {
        l0 = fmaf(a[f], sW2[0 * DF + f], l0);
        l1 = fmaf(a[f], sW2[1 * DF + f], l1);
        l2 = fmaf(a[f], sW2[2 * DF + f], l2);
    }
    float m = fmaxf(l0, fmaxf(l1, l2));
    float* wout = g_w + (it * N + n) * 3;
    wout[0] = expf(l0 - m);
    wout[1] = expf(l1 - m);
    wout[2] = expf(l2 - m);
}

// ---------------------------------------------------------------------------
// Flat mean-shift pair loop, minimal instruction count (22 / packed pair),
// fused finalize (last block per i-stripe; R8-proven protocol).
// ---------------------------------------------------------------------------
__global__ void __launch_bounds__(ITILE, 5) shift_kernel(float* __restrict__ out, int it) {
    __shared__ __align__(16) float sj[PCHUNK * 16];   // 20.5 KB tile
    __shared__ int s_last;

    const float* srcP = (it & 1) ? g_pairsB : g_pairsA;
    float*       dstP = (it & 1) ? g_pairsA : g_pairsB;

    int js  = blockIdx.y;
    int bx  = blockIdx.x;
    int tid = threadIdx.x;

    const float4* src = (const float4*)(srcP + js * PCHUNK * 16);
    float4* d4 = (float4*)sj;
    for (int t = tid; t < PCHUNK * 4; t += ITILE) d4[t] = src[t];
    __syncthreads();

    int slot = bx * ITILE + tid;      // < NSLOTS (grid covers exactly NSLOTS)
    int pb = (slot >> 1) * 16, h = slot & 1;
    float xi  = srcP[pb + 0 + h];
    float yi  = srcP[pb + 2 + h];
    float zi  = srcP[pb + 4 + h];
    float nui = srcP[pb + 6 + h];
    // d <= bw^2  <=>  (xi.xj - 0.5|xj|^2) >= 0.5|xi|^2 - 0.5 bw^2
    float th1 = -nui - 0.02f;    // bw=0.2
    float th2 = -nui - 1.445f;   // bw=1.7
    float th3 = -nui - 5.12f;    // bw=3.2

    unsigned long long xi2, yi2, zi2;
    asm("mov.b64 %0, {%1, %1};" : "=l"(xi2) : "f"(xi));
    asm("mov.b64 %0, {%1, %1};" : "=l"(yi2) : "f"(yi));
    asm("mov.b64 %0, {%1, %1};" : "=l"(zi2) : "f"(zi));

    // per-band packed accumulators: (sumx,sumy) and (sumz,count)
    unsigned long long axy1 = 0ull, axy2 = 0ull, axy3 = 0ull;
    unsigned long long azc1 = 0ull, azc2 = 0ull, azc3 = 0ull;

    const ulonglong2* tile = (const ulonglong2*)sj;
    #pragma unroll 4
    for (int p = 0; p < PCHUNK; p++) {
        ulonglong2 rA = tile[4 * p + 0];   // (x01, y01)
        ulonglong2 rB = tile[4 * p + 1];   // (z01, nu01)
        ulonglong2 rC = tile[4 * p + 2];   // (xy0, xy1)
        ulonglong2 rD = tile[4 * p + 3];   // (zc0, zc1)
        asm("{\n\t"
            ".reg .b64  t64;\n\t"
            ".reg .f32  vl, vh;\n\t"
            ".reg .pred pl1, pl2, pl3, ph1, ph2, ph3;\n\t"
            "fma.rn.f32x2 t64, %6, %9, %12;\n\t"     // xi*xj - 0.5|xj|^2
            "fma.rn.f32x2 t64, %7, %10, t64;\n\t"
            "fma.rn.f32x2 t64, %8, %11, t64;\n\t"
            "mov.b64 {vl, vh}, t64;\n\t"
            "setp.ge.f32 pl1, vl, %13;\n\t"
            "setp.ge.f32 pl2, vl, %14;\n\t"
            "setp.ge.f32 pl3, vl, %15;\n\t"
            "setp.ge.f32 ph1, vh, %13;\n\t"
            "setp.ge.f32 ph2, vh, %14;\n\t"
            "setp.ge.f32 ph3, vh, %15;\n\t"
            "@pl1 add.rn.f32x2 %0, %0, %16;\n\t"
            "@pl1 add.rn.f32x2 %3, %3, %18;\n\t"
            "@pl2 add.rn.f32x2 %1, %1, %16;\n\t"
            "@pl2 add.rn.f32x2 %4, %4, %18;\n\t"
            "@pl3 add.rn.f32x2 %2, %2, %16;\n\t"
            "@pl3 add.rn.f32x2 %5, %5, %18;\n\t"
            "@ph1 add.rn.f32x2 %0, %0, %17;\n\t"
            "@ph1 add.rn.f32x2 %3, %3, %19;\n\t"
            "@ph2 add.rn.f32x2 %1, %1, %17;\n\t"
            "@ph2 add.rn.f32x2 %4, %4, %19;\n\t"
            "@ph3 add.rn.f32x2 %2, %2, %17;\n\t"
            "@ph3 add.rn.f32x2 %5, %5, %19;\n\t"
            "}"
            : "+l"(axy1), "+l"(axy2), "+l"(axy3),
              "+l"(azc1), "+l"(azc2), "+l"(azc3)
            : "l"(xi2), "l"(yi2), "l"(zi2),
              "l"(rA.x), "l"(rA.y), "l"(rB.x), "l"(rB.y),
              "f"(th1), "f"(th2), "f"(th3),
              "l"(rC.x), "l"(rC.y), "l"(rD.x), "l"(rD.y));
    }

    float* dst = g_part + (js * NSLOTS + slot) * 12;
    ((float4*)dst)[0] = make_float4(
        __uint_as_float((unsigned)axy1), __uint_as_float((unsigned)(axy1 >> 32)),
        __uint_as_float((unsigned)axy2), __uint_as_float((unsigned)(axy2 >> 32)));
    ((float4*)dst)[1] = make_float4(
        __uint_as_float((unsigned)axy3), __uint_as_float((unsigned)(axy3 >> 32)),
        __uint_as_float((unsigned)azc1), __uint_as_float((unsigned)(azc1 >> 32)));
    ((float4*)dst)[2] = make_float4(
        __uint_as_float((unsigned)azc2), __uint_as_float((unsigned)(azc2 >> 32)),
        __uint_as_float((unsigned)azc3), __uint_as_float((unsigned)(azc3 >> 32)));

    // last-block finalize for this i-stripe (R8-proven protocol)
    __threadfence();
    __syncthreads();
    if (tid == 0) {
        int old = atomicAdd(&g_cnt[it * NITILE + bx], 1);
        s_last = (old == JSPLIT - 1) ? 1 : 0;
    }
    __syncthreads();
    if (!s_last) return;
    __threadfence();

    float nx = SENTC, ny = SENTC, nz = SENTC;
    if (slot < N) {
        float sx1=0,sy1=0,sx2=0,sy2=0,sx3=0,sy3=0;
        float sz1=0,c1=0,sz2=0,c2=0,sz3=0,c3=0;
        #pragma unroll 4
        for (int js2 = 0; js2 < JSPLIT; js2++) {
            const float4* p = (const float4*)(g_part + (js2 * NSLOTS + slot) * 12);
            float4 v0 = p[0], v1 = p[1], v2 = p[2];
            sx1 += v0.x; sy1 += v0.y; sx2 += v0.z; sy2 += v0.w;
            sx3 += v1.x; sy3 += v1.y; sz1 += v1.z; c1  += v1.w;
            sz2 += v2.x; c2  += v2.y; sz3 += v2.z; c3  += v2.w;
        }
        const float* wp = g_w + (it * N + slot) * 3;
        float e0 = wp[0], e1 = wp[1], e2 = wp[2];
        float inv = 1.0f / (e0 + e1 + e2);
        float r1 = e0 / c1, r2 = e1 / c2, r3 = e2 / c3;
        nx = (sx1 * r1 + sx2 * r2 + sx3 * r3) * inv;
        ny = (sy1 * r1 + sy2 * r2 + sy3 * r3) * inv;
        nz = (sz1 * r1 + sz2 * r2 + sz3 * r3) * inv;
        float* oo = out + (it * N + slot) * 3;
        oo[0] = nx; oo[1] = ny; oo[2] = nz;
    }
    if (it < ITERS - 1) write_rec(dstP, slot, nx, ny, nz);
}

// ---------------------------------------------------------------------------
// Inputs: 0:X 1:X_fea 2:W1 3:b1 4:gamma 5:beta 6:W2 7:b2   Output: [4,N,3] f32
// Launch order: shift(it=0) at index 3 (ncu capture point). 7 launches total.
// ---------------------------------------------------------------------------
extern "C" void kernel_launch(void* const* d_in, const int* in_sizes, int n_in,
                              void* d_out, int out_size) {
    const float* X     = (const float*)d_in[0];
    const float* Xfea  = (const float*)d_in[1];
    const float* W1    = (const float*)d_in[2];
    const float* b1    = (const float*)d_in[3];
    const float* gamma = (const float*)d_in[4];
    const float* beta  = (const float*)d_in[5];
    const float* W2    = (const float*)d_in[6];
    const float* b2    = (const float*)d_in[7];
    float* out = (float*)d_out;

    linear1_kernel<<<dim3((N + 127) / 128, ITERS), 128>>>(Xfea, W1, b1);        // 0
    bnstats_prep_kernel<<<ITERS, 1024>>>(X);                                     // 1
    logits_kernel<<<dim3((N + 255) / 256, ITERS), 256>>>(gamma, beta, W2, b2);   // 2
    for (int it = 0; it < ITERS; it++)                                           // 3..6
        shift_kernel<<<dim3(NITILE, JSPLIT), ITILE>>>(out, it);
}

// round 11
// speedup vs baseline: 1.8056x; 1.3577x over previous
#include <cuda_runtime.h>
#include <math.h>

// Problem constants
#define N        10000
#define DF       32
#define ITERS    4
#define JSPLIT   18             // j-range splits
#define PCHUNK   285            // packed j-pairs per split (570 j), 57*5
#define NPAIR_PAD (JSPLIT * PCHUNK)    // 5130 pairs = 10260 j slots
#define NSLOTS_J (2 * NPAIR_PAD)       // 10260
#define ITILE    256
#define NITILE   40             // i-slots 10240; grid 40*18=720, 1 wave @ occ 5
#define NSLOTS_I 10240
#define ZSCALE   16384.0f
#define SENTC    1.0e6f

// Scratch (static device arrays; cudaMalloc is forbidden)
__device__ float g_pairsA[NPAIR_PAD * 16];
__device__ float g_pairsB[NPAIR_PAD * 16];
__device__ int   g_cnt[ITERS * NITILE];        // stripe completion counters
__device__ float g_part[JSPLIT * NSLOTS_I * 12];
__device__ float g_h[ITERS * N * DF];
__device__ float g_stats[ITERS * DF * 2];
__device__ float g_w[ITERS * N * 3];

// ---------------------------------------------------------------------------
// Pair record (16 words per packed j-pair):
//   [0..7]  x0 x1 y0 y1 z0 z1 nu0 nu1   (nu = -0.5|x|^2)
//   [8..11] x0 y0 x1 y1                  (xy addends)
//   [12,13] round(z*2^14) s32            (z fixed-point)
// ---------------------------------------------------------------------------
__device__ __forceinline__ void write_rec(float* buf, int s, float x, float y, float z) {
    int p = s >> 1, h = s & 1;
    float nu = -0.5f * (x * x + y * y + z * z);
    float* rec = buf + p * 16;
    rec[0 + h] = x;
    rec[2 + h] = y;
    rec[4 + h] = z;
    rec[6 + h] = nu;
    rec[8 + 2 * h] = x;
    rec[9 + 2 * h] = y;
    ((int*)rec)[12 + h] = __float2int_rn(z * ZSCALE);
}

// ---------------------------------------------------------------------------
// Logits pipeline
// ---------------------------------------------------------------------------
__global__ void linear1_kernel(const float* __restrict__ Xfea,
                               const float* __restrict__ W1,
                               const float* __restrict__ b1) {
    int it = blockIdx.y;
    int n  = blockIdx.x * blockDim.x + threadIdx.x;
    __shared__ float sW[DF * DF];
    __shared__ float sb[DF];
    for (int k = threadIdx.x; k < DF * DF; k += blockDim.x) sW[k] = W1[it * DF * DF + k];
    if (threadIdx.x < DF) sb[threadIdx.x] = b1[it * DF + threadIdx.x];
    __syncthreads();
    if (n >= N) return;
    float xf[DF];
    const float4* xr = (const float4*)(Xfea + n * DF);
    #pragma unroll
    for (int q = 0; q < DF / 4; q++) {
        float4 v = xr[q];
        xf[4*q] = v.x; xf[4*q+1] = v.y; xf[4*q+2] = v.z; xf[4*q+3] = v.w;
    }
    float* hout = g_h + (it * N + n) * DF;
    #pragma unroll 4
    for (int f = 0; f < DF; f++) {
        float acc = sb[f];
        #pragma unroll
        for (int k = 0; k < DF; k++) acc = fmaf(xf[k], sW[f * DF + k], acc);
        hout[f] = acc;
    }
}

// BN stats + fused pair-record prep (both buffers' sentinel tails) + counters.
__global__ void __launch_bounds__(1024, 1) bnstats_prep_kernel(const float* __restrict__ X) {
    int it = blockIdx.x;
    int tid = threadIdx.x;
    int w  = tid >> 5;
    int f  = tid & 31;
    float s = 0.f, sq = 0.f;
    for (int n = w; n < N; n += 32) {
        float v = g_h[(it * N + n) * DF + f];
        s += v;
        sq = fmaf(v, v, sq);
    }
    __shared__ float ss[32 * 33];
    __shared__ float sqq[32 * 33];
    ss [w * 33 + f] = s;
    sqq[w * 33 + f] = sq;
    __syncthreads();
    if (tid < DF) {
        float ts = 0.f, tq = 0.f;
        for (int ww = 0; ww < 32; ww++) { ts += ss[ww * 33 + f]; tq += sqq[ww * 33 + f]; }
        float mu  = ts / (float)N;
        float var = tq / (float)N - mu * mu;   // biased var (matches reference)
        g_stats[(it * DF + f) * 2 + 0] = mu;
        g_stats[(it * DF + f) * 2 + 1] = rsqrtf(var + 1e-5f);
    }
    // fused prep across the 4 blocks (gtid 0..4095)
    int gtid = blockIdx.x * 1024 + tid;
    for (int sl = gtid; sl < NSLOTS_J; sl += 4096) {
        if (sl < N) write_rec(g_pairsA, sl, X[3*sl], X[3*sl+1], X[3*sl+2]);
        else        write_rec(g_pairsA, sl, SENTC, SENTC, SENTC);
        // B buffer: slots < NSLOTS_I are rewritten by shift each iter; the
        // tail (NSLOTS_I..NSLOTS_J) must be sentinel-filled once here.
        if (sl >= NSLOTS_I) write_rec(g_pairsB, sl, SENTC, SENTC, SENTC);
    }
    if (gtid < ITERS * NITILE) g_cnt[gtid] = 0;
}

__global__ void logits_kernel(const float* __restrict__ gamma,
                              const float* __restrict__ beta,
                              const float* __restrict__ W2,
                              const float* __restrict__ b2) {
    int it = blockIdx.y;
    int n  = blockIdx.x * blockDim.x + threadIdx.x;
    __shared__ float sg[DF], sbe[DF], smu[DF], sis[DF], sW2[3 * DF], sb2[3];
    if (threadIdx.x < DF) {
        sg [threadIdx.x] = gamma[it * DF + threadIdx.x];
        sbe[threadIdx.x] = beta [it * DF + threadIdx.x];
        smu[threadIdx.x] = g_stats[(it * DF + threadIdx.x) * 2 + 0];
        sis[threadIdx.x] = g_stats[(it * DF + threadIdx.x) * 2 + 1];
    }
    if (threadIdx.x < 3 * DF) sW2[threadIdx.x] = W2[it * 3 * DF + threadIdx.x];
    if (threadIdx.x < 3)      sb2[threadIdx.x] = b2[it * 3 + threadIdx.x];
    __syncthreads();
    if (n >= N) return;
    const float* hrow = g_h + (it * N + n) * DF;
    float a[DF];
    #pragma unroll
    for (int f = 0; f < DF; f++) {
        float v = (hrow[f] - smu[f]) * sis[f] * sg[f] + sbe[f];
        a[f] = fmaxf(v, 0.f);
    }
    float l0 = sb2[0], l1 = sb2[1], l2 = sb2[2];
    #pragma unroll
    for (int f = 0; f < DF; f++) {
        l0 = fmaf(a[f], sW2[0 * DF + f], l0);
        l1 = fmaf(a[f], sW2[1 * DF + f], l1);
        l2 = fmaf(a[f], sW2[2 * DF + f], l2);
    }
    float m = fmaxf(l0, fmaxf(l1, l2));
    float* wout = g_w + (it * N + n) * 3;
    wout[0] = expf(l0 - m);
    wout[1] = expf(l1 - m);
    wout[2] = expf(l2 - m);
}

// ---------------------------------------------------------------------------
// Mean-shift pair loop (R4's measured-fastest body) + fused finalize.
// ---------------------------------------------------------------------------
__global__ void __launch_bounds__(ITILE, 5) shift_kernel(float* __restrict__ out, int it) {
    __shared__ __align__(16) float sj[PCHUNK * 16];   // 18.2 KB tile
    __shared__ int s_last;

    const float* srcP = (it & 1) ? g_pairsB : g_pairsA;
    float*       dstP = (it & 1) ? g_pairsA : g_pairsB;

    int js  = blockIdx.y;
    int bx  = blockIdx.x;
    int tid = threadIdx.x;

    const float4* src = (const float4*)(srcP + js * PCHUNK * 16);
    float4* d4 = (float4*)sj;
    for (int t = tid; t < PCHUNK * 4; t += ITILE) d4[t] = src[t];
    __syncthreads();

    int slot = bx * ITILE + tid;     // < NSLOTS_I
    int pb = (slot >> 1) * 16, h = slot & 1;
    float xi  = srcP[pb + 0 + h];
    float yi  = srcP[pb + 2 + h];
    float zi  = srcP[pb + 4 + h];
    float nui = srcP[pb + 6 + h];
    // d <= bw^2  <=>  (xi.xj - 0.5|xj|^2) >= 0.5|xi|^2 - 0.5 bw^2
    float th1 = -nui - 0.02f;    // bw=0.2
    float th2 = -nui - 1.445f;   // bw=1.7
    float th3 = -nui - 5.12f;    // bw=3.2

    unsigned long long xi2, yi2, zi2;
    asm("mov.b64 %0, {%1, %1};" : "=l"(xi2) : "f"(xi));
    asm("mov.b64 %0, {%1, %1};" : "=l"(yi2) : "f"(yi));
    asm("mov.b64 %0, {%1, %1};" : "=l"(zi2) : "f"(zi));

    unsigned long long axy1 = 0ull, axy2 = 0ull, axy3 = 0ull;  // (sumx,sumy)
    int   az1 = 0, az2 = 0, az3 = 0;                           // fixed-point z
    int   ac1 = 0, ac2 = 0;                                    // counts 1,2
    float fc3 = 0.0f;                                          // count 3

    #pragma unroll 5
    for (int p = 0; p < PCHUNK; p++) {
        const float* rec = sj + p * 16;
        unsigned long long x01  = *(const unsigned long long*)(rec + 0);
        unsigned long long y01  = *(const unsigned long long*)(rec + 2);
        unsigned long long z01  = *(const unsigned long long*)(rec + 4);
        unsigned long long nu01 = *(const unsigned long long*)(rec + 6);
        unsigned long long xy0  = *(const unsigned long long*)(rec + 8);
        unsigned long long xy1  = *(const unsigned long long*)(rec + 10);
        int zf0 = ((const int*)rec)[12];
        int zf1 = ((const int*)rec)[13];
        asm("{\n\t"
            ".reg .b64  t64;\n\t"
            ".reg .f32  vl, vh;\n\t"
            ".reg .pred pl1, pl2, pl3, ph1, ph2, ph3;\n\t"
            "fma.rn.f32x2 t64, %9, %12, %15;\n\t"    // xi*xj - 0.5|xj|^2
            "fma.rn.f32x2 t64, %10, %13, t64;\n\t"
            "fma.rn.f32x2 t64, %11, %14, t64;\n\t"
            "mov.b64 {vl, vh}, t64;\n\t"
            "setp.ge.f32 pl1, vl, %16;\n\t"
            "setp.ge.f32 pl2, vl, %17;\n\t"
            "setp.ge.f32 pl3, vl, %18;\n\t"
            "setp.ge.f32 ph1, vh, %16;\n\t"
            "setp.ge.f32 ph2, vh, %17;\n\t"
            "setp.ge.f32 ph3, vh, %18;\n\t"
            "@pl1 add.rn.f32x2 %0, %0, %19;\n\t"
            "@pl1 add.s32 %3, %3, %21;\n\t"
            "@pl1 add.s32 %6, %6, 1;\n\t"
            "@pl2 add.rn.f32x2 %1, %1, %19;\n\t"
            "@pl2 add.s32 %4, %4, %21;\n\t"
            "@pl2 add.s32 %7, %7, 1;\n\t"
            "@pl3 add.rn.f32x2 %2, %2, %19;\n\t"
            "@pl3 add.s32 %5, %5, %21;\n\t"
            "@pl3 add.f32 %8, %8, 0F3F800000;\n\t"
            "@ph1 add.rn.f32x2 %0, %0, %20;\n\t"
            "@ph1 add.s32 %3, %3, %22;\n\t"
            "@ph1 add.s32 %6, %6, 1;\n\t"
            "@ph2 add.rn.f32x2 %1, %1, %20;\n\t"
            "@ph2 add.s32 %4, %4, %22;\n\t"
            "@ph2 add.s32 %7, %7, 1;\n\t"
            "@ph3 add.rn.f32x2 %2, %2, %20;\n\t"
            "@ph3 add.s32 %5, %5, %22;\n\t"
            "@ph3 add.f32 %8, %8, 0F3F800000;\n\t"
            "}"
            : "+l"(axy1), "+l"(axy2), "+l"(axy3),
              "+r"(az1), "+r"(az2), "+r"(az3),
              "+r"(ac1), "+r"(ac2), "+f"(fc3)
            : "l"(xi2), "l"(yi2), "l"(zi2),
              "l"(x01), "l"(y01), "l"(z01), "l"(nu01),
              "f"(th1), "f"(th2), "f"(th3),
              "l"(xy0), "l"(xy1), "r"(zf0), "r"(zf1));
    }

    float* dst = g_part + (js * NSLOTS_I + slot) * 12;
    ((float4*)dst)[0] = make_float4(
        __uint_as_float((unsigned)axy1), __uint_as_float((unsigned)(axy1 >> 32)),
        __uint_as_float((unsigned)axy2), __uint_as_float((unsigned)(axy2 >> 32)));
    ((float4*)dst)[1] = make_float4(
        __uint_as_float((unsigned)axy3), __uint_as_float((unsigned)(axy3 >> 32)),
        __int_as_float(az1), __int_as_float(az2));
    ((float4*)dst)[2] = make_float4(
        __int_as_float(az3), __int_as_float(ac1),
        __int_as_float(ac2), fc3);

    // last-block finalize for this i-stripe (R8-proven protocol)
    __threadfence();
    __syncthreads();
    if (tid == 0) {
        int old = atomicAdd(&g_cnt[it * NITILE + bx], 1);
        s_last = (old == JSPLIT - 1) ? 1 : 0;
    }
    __syncthreads();
    if (!s_last) return;
    __threadfence();

    float nx = SENTC, ny = SENTC, nz = SENTC;
    if (slot < N) {
        float sx1=0,sy1=0,sx2=0,sy2=0,sx3=0,sy3=0, c3=0.f;
        int   z1=0,z2=0,z3=0, c1=0,c2=0;
        #pragma unroll 3
        for (int js2 = 0; js2 < JSPLIT; js2++) {
            const float4* p = (const float4*)(g_part + (js2 * NSLOTS_I + slot) * 12);
            float4 v0 = p[0], v1 = p[1], v2 = p[2];
            sx1 += v0.x; sy1 += v0.y; sx2 += v0.z; sy2 += v0.w;
            sx3 += v1.x; sy3 += v1.y;
            z1 += __float_as_int(v1.z); z2 += __float_as_int(v1.w);
            z3 += __float_as_int(v2.x);
            c1 += __float_as_int(v2.y); c2 += __float_as_int(v2.z); c3 += v2.w;
        }
        float sz1 = (float)z1 * (1.0f / ZSCALE);
        float sz2 = (float)z2 * (1.0f / ZSCALE);
        float sz3 = (float)z3 * (1.0f / ZSCALE);
        const float* wp = g_w + (it * N + slot) * 3;
        float e0 = wp[0], e1 = wp[1], e2 = wp[2];
        float inv = 1.0f / (e0 + e1 + e2);
        float r1 = e0 / (float)c1, r2 = e1 / (float)c2, r3 = e2 / c3;
        nx = (sx1 * r1 + sx2 * r2 + sx3 * r3) * inv;
        ny = (sy1 * r1 + sy2 * r2 + sy3 * r3) * inv;
        nz = (sz1 * r1 + sz2 * r2 + sz3 * r3) * inv;
        float* oo = out + (it * N + slot) * 3;
        oo[0] = nx; oo[1] = ny; oo[2] = nz;
    }
    if (it < ITERS - 1) write_rec(dstP, slot, nx, ny, nz);
}

// ---------------------------------------------------------------------------
// Inputs: 0:X 1:X_fea 2:W1 3:b1 4:gamma 5:beta 6:W2 7:b2   Output: [4,N,3] f32
// Launch order: shift(it=0) at index 3 (ncu capture point). 7 launches total.
// ---------------------------------------------------------------------------
extern "C" void kernel_launch(void* const* d_in, const int* in_sizes, int n_in,
                              void* d_out, int out_size) {
    const float* X     = (const float*)d_in[0];
    const float* Xfea  = (const float*)d_in[1];
    const float* W1    = (const float*)d_in[2];
    const float* b1    = (const float*)d_in[3];
    const float* gamma = (const float*)d_in[4];
    const float* beta  = (const float*)d_in[5];
    const float* W2    = (const float*)d_in[6];
    const float* b2    = (const float*)d_in[7];
    float* out = (float*)d_out;

    linear1_kernel<<<dim3((N + 127) / 128, ITERS), 128>>>(Xfea, W1, b1);        // 0
    bnstats_prep_kernel<<<ITERS, 1024>>>(X);                                     // 1
    logits_kernel<<<dim3((N + 255) / 256, ITERS), 256>>>(gamma, beta, W2, b2);   // 2
    for (int it = 0; it < ITERS; it++)                                           // 3..6
        shift_kernel<<<dim3(NITILE, JSPLIT), ITILE>>>(out, it);
}